// round 2
// baseline (speedup 1.0000x reference)
#include <cuda_runtime.h>
#include <cuda_bf16.h>
#include <cstdint>

// KVDequantizer: Q4 nibble unpack + per-block (32 elems) scale/bias dequant.
// One thread handles ONE 32-element block:
//   reads  4 x int4  (16 packed ints, 64B)
//   reads  1 x scale, 1 x bias
//   writes 8 x float4 (32 floats, 128B)
// Streaming hints (__ldcs/__stcs): zero-reuse data, evict-first in L2.

static constexpr int BATCH    = 2;
static constexpr int N_BLOCKS = 131072;
static constexpr int BLOCKS_PER_TENSOR = BATCH * N_BLOCKS;          // 262,144
static constexpr int TOTAL_BLOCKS      = 2 * BLOCKS_PER_TENSOR;     // 524,288 (K+V)
static constexpr long long FLOATS_PER_TENSOR =
    (long long)BLOCKS_PER_TENSOR * 32;                              // 8,388,608

__global__ __launch_bounds__(256)
void kv_dequant_kernel(const int4* __restrict__ kp,
                       const float* __restrict__ ks,
                       const float* __restrict__ kb,
                       const int4* __restrict__ vp,
                       const float* __restrict__ vs,
                       const float* __restrict__ vb,
                       float4* __restrict__ out)
{
    int i = blockIdx.x * blockDim.x + threadIdx.x;   // 0 .. TOTAL_BLOCKS-1

    const int4*  src;
    const float* sp;
    const float* bp;
    float4*      dst;
    int blk;
    if (i < BLOCKS_PER_TENSOR) {                     // K half
        blk = i;
        src = kp; sp = ks; bp = kb;
        dst = out;
    } else {                                         // V half
        blk = i - BLOCKS_PER_TENSOR;
        src = vp; sp = vs; bp = vb;
        dst = out + FLOATS_PER_TENSOR / 4;
    }

    // 4 independent 16B loads (MLP_p1 = 4) + 2 scalar loads, all issued up front.
    const int4* p4 = src + (long long)blk * 4;
    int4 p0 = __ldcs(p4 + 0);
    int4 p1 = __ldcs(p4 + 1);
    int4 p2 = __ldcs(p4 + 2);
    int4 p3 = __ldcs(p4 + 3);
    float s = __ldg(sp + blk);
    float b = __ldg(bp + blk);

    float4* d = dst + (long long)blk * 8;

    // Each packed int32 (0..255): out[2m] = low nibble, out[2m+1] = high nibble.
    #define DEQ2(v) make_float4(fmaf((float)((v).x & 15), s, b), \
                                fmaf((float)((v).x >> 4), s, b), \
                                fmaf((float)((v).y & 15), s, b), \
                                fmaf((float)((v).y >> 4), s, b)), \
                    make_float4(fmaf((float)((v).z & 15), s, b), \
                                fmaf((float)((v).z >> 4), s, b), \
                                fmaf((float)((v).w & 15), s, b), \
                                fmaf((float)((v).w >> 4), s, b))

    {
        float4 a0, a1; { float4 t0, t1; t0 = make_float4(
            fmaf((float)(p0.x & 15), s, b), fmaf((float)(p0.x >> 4), s, b),
            fmaf((float)(p0.y & 15), s, b), fmaf((float)(p0.y >> 4), s, b));
          t1 = make_float4(
            fmaf((float)(p0.z & 15), s, b), fmaf((float)(p0.z >> 4), s, b),
            fmaf((float)(p0.w & 15), s, b), fmaf((float)(p0.w >> 4), s, b));
          a0 = t0; a1 = t1; }
        __stcs(d + 0, a0);
        __stcs(d + 1, a1);
    }
    {
        float4 a0 = make_float4(
            fmaf((float)(p1.x & 15), s, b), fmaf((float)(p1.x >> 4), s, b),
            fmaf((float)(p1.y & 15), s, b), fmaf((float)(p1.y >> 4), s, b));
        float4 a1 = make_float4(
            fmaf((float)(p1.z & 15), s, b), fmaf((float)(p1.z >> 4), s, b),
            fmaf((float)(p1.w & 15), s, b), fmaf((float)(p1.w >> 4), s, b));
        __stcs(d + 2, a0);
        __stcs(d + 3, a1);
    }
    {
        float4 a0 = make_float4(
            fmaf((float)(p2.x & 15), s, b), fmaf((float)(p2.x >> 4), s, b),
            fmaf((float)(p2.y & 15), s, b), fmaf((float)(p2.y >> 4), s, b));
        float4 a1 = make_float4(
            fmaf((float)(p2.z & 15), s, b), fmaf((float)(p2.z >> 4), s, b),
            fmaf((float)(p2.w & 15), s, b), fmaf((float)(p2.w >> 4), s, b));
        __stcs(d + 4, a0);
        __stcs(d + 5, a1);
    }
    {
        float4 a0 = make_float4(
            fmaf((float)(p3.x & 15), s, b), fmaf((float)(p3.x >> 4), s, b),
            fmaf((float)(p3.y & 15), s, b), fmaf((float)(p3.y >> 4), s, b));
        float4 a1 = make_float4(
            fmaf((float)(p3.z & 15), s, b), fmaf((float)(p3.z >> 4), s, b),
            fmaf((float)(p3.w & 15), s, b), fmaf((float)(p3.w >> 4), s, b));
        __stcs(d + 6, a0);
        __stcs(d + 7, a1);
    }
    #undef DEQ2
}

extern "C" void kernel_launch(void* const* d_in, const int* in_sizes, int n_in,
                              void* d_out, int out_size)
{
    const int4*  kp = (const int4*) d_in[0];
    const float* ks = (const float*)d_in[1];
    const float* kb = (const float*)d_in[2];
    const int4*  vp = (const int4*) d_in[3];
    const float* vs = (const float*)d_in[4];
    const float* vb = (const float*)d_in[5];
    float4* out = (float4*)d_out;

    const int tpb = 256;
    const int blocks = TOTAL_BLOCKS / tpb;          // 2048 CTAs
    kv_dequant_kernel<<<blocks, tpb>>>(kp, ks, kb, vp, vs, vb, out);
}

// round 3
// speedup vs baseline: 1.1794x; 1.1794x over previous
#include <cuda_runtime.h>
#include <cuda_bf16.h>
#include <cstdint>

// KVDequantizer: Q4 nibble unpack + per-block (32 elems) scale/bias dequant.
//
// Persistent grid-stride kernel with 1-deep software-pipelined prefetch:
// work item = 1 int4 (4 packed ints -> 8 floats). Each iteration issues the
// NEXT item's loads before dequantizing/storing the current one, so memory
// latency is only exposed once per thread instead of once per wave.

static constexpr int BATCH    = 2;
static constexpr int N_BLOCKS = 131072;
static constexpr long long PACKED_PER_TENSOR =
    (long long)BATCH * N_BLOCKS * 16;                 // 4,194,304 int32
static constexpr int NVEC  = (int)(PACKED_PER_TENSOR / 4);   // 1,048,576 int4 items / tensor
static constexpr int TOTAL = 2 * NVEC;                        // 2,097,152 items (K+V)

__global__ __launch_bounds__(256)
void kv_dequant_kernel(const int4* __restrict__ kp,
                       const float* __restrict__ ks,
                       const float* __restrict__ kb,
                       const int4* __restrict__ vp,
                       const float* __restrict__ vs,
                       const float* __restrict__ vb,
                       float4* __restrict__ out)
{
    const int stride = gridDim.x * blockDim.x;
    int i = blockIdx.x * blockDim.x + threadIdx.x;
    if (i >= TOTAL) return;

    // ---- load for item i (prologue) ----
    auto load_item = [&](int idx, int4& p, float& s, float& b) {
        int j, blk;
        if (idx < NVEC) {
            j = idx;
            p = __ldg(kp + j);
            blk = j >> 2;
            s = __ldg(ks + blk);
            b = __ldg(kb + blk);
        } else {
            j = idx - NVEC;
            p = __ldg(vp + j);
            blk = j >> 2;
            s = __ldg(vs + blk);
            b = __ldg(vb + blk);
        }
    };

    int4 p; float s, b;
    load_item(i, p, s, b);

    while (true) {
        int inext = i + stride;

        // Prefetch next item's data before touching current results.
        int4 pn; float sn, bn;
        bool has_next = (inext < TOTAL);
        if (has_next) load_item(inext, pn, sn, bn);

        // ---- dequant + store current item ----
        // Output offset: item idx -> 8 floats -> 2 float4 slots. K half maps
        // directly; V half continues after NVEC*2 float4 slots.
        long long o = (long long)i * 2;   // works for both halves: V items have
                                          // idx >= NVEC, landing at >= NVEC*2.
        float4 o0, o1;
        o0.x = fmaf((float)(p.x & 15), s, b);
        o0.y = fmaf((float)(p.x >> 4), s, b);
        o0.z = fmaf((float)(p.y & 15), s, b);
        o0.w = fmaf((float)(p.y >> 4), s, b);
        o1.x = fmaf((float)(p.z & 15), s, b);
        o1.y = fmaf((float)(p.z >> 4), s, b);
        o1.z = fmaf((float)(p.w & 15), s, b);
        o1.w = fmaf((float)(p.w >> 4), s, b);
        out[o]     = o0;
        out[o + 1] = o1;

        if (!has_next) break;
        p = pn; s = sn; b = bn;
        i = inext;
    }
}

extern "C" void kernel_launch(void* const* d_in, const int* in_sizes, int n_in,
                              void* d_out, int out_size)
{
    const int4*  kp = (const int4*) d_in[0];
    const float* ks = (const float*)d_in[1];
    const float* kb = (const float*)d_in[2];
    const int4*  vp = (const int4*) d_in[3];
    const float* vs = (const float*)d_in[4];
    const float* vb = (const float*)d_in[5];
    float4* out = (float4*)d_out;

    // Full residency: 148 SMs x 8 CTAs of 256 threads (2048 threads/SM).
    const int tpb  = 256;
    const int ctas = 148 * 8;   // 1184 CTAs -> 303,104 threads, ~7 items each
    kv_dequant_kernel<<<ctas, tpb>>>(kp, ks, kb, vp, vs, vb, out);
}

// round 4
// speedup vs baseline: 1.4349x; 1.2166x over previous
#include <cuda_runtime.h>
#include <cuda_bf16.h>
#include <cstdint>

// KVDequantizer: Q4 nibble unpack + per-block (32 elems) scale/bias dequant.
//
// R4: move the 64MB store stream OFF the per-warp STG/L1tex path.
//   - each thread: 1x LDG.128 (4 packed ints) + scale/bias, dequant -> 8 floats
//   - STS 32B into SMEM staging buffer (8KB per CTA)
//   - one cp.async.bulk (TMA bulk store, shared::cta -> global) per CTA
// Loads keep the L1tex queue to themselves; writes ride the async TMA engine.

static constexpr int BATCH    = 2;
static constexpr int N_BLOCKS = 131072;
static constexpr long long PACKED_PER_TENSOR =
    (long long)BATCH * N_BLOCKS * 16;                      // 4,194,304 int32
static constexpr int NVEC  = (int)(PACKED_PER_TENSOR / 4); // 1,048,576 int4 items/tensor
static constexpr int TOTAL = 2 * NVEC;                     // 2,097,152 items (K+V)
static constexpr int TPB   = 256;
static constexpr int CTA_OUT_BYTES = TPB * 32;             // 8192 B per CTA

__global__ __launch_bounds__(TPB)
void kv_dequant_kernel(const int4* __restrict__ kp,
                       const float* __restrict__ ks,
                       const float* __restrict__ kb,
                       const int4* __restrict__ vp,
                       const float* __restrict__ vs,
                       const float* __restrict__ vb,
                       float* __restrict__ out)
{
    __shared__ __align__(128) float4 buf[TPB * 2];         // 8192 B staging

    const int tid = threadIdx.x;
    const int i   = blockIdx.x * TPB + tid;                // int4 item index

    // ---- gather inputs (only loads touch L1tex) ----
    int4 p; float s, b;
    if (i < NVEC) {
        p = __ldg(kp + i);
        s = __ldg(ks + (i >> 2));
        b = __ldg(kb + (i >> 2));
    } else {
        int j = i - NVEC;
        p = __ldg(vp + j);
        s = __ldg(vs + (j >> 2));
        b = __ldg(vb + (j >> 2));
    }

    // ---- dequant: low nibble first, then high nibble ----
    float4 o0, o1;
    o0.x = fmaf((float)(p.x & 15), s, b);
    o0.y = fmaf((float)(p.x >> 4), s, b);
    o0.z = fmaf((float)(p.y & 15), s, b);
    o0.w = fmaf((float)(p.y >> 4), s, b);
    o1.x = fmaf((float)(p.z & 15), s, b);
    o1.y = fmaf((float)(p.z >> 4), s, b);
    o1.z = fmaf((float)(p.w & 15), s, b);
    o1.w = fmaf((float)(p.w >> 4), s, b);

    buf[tid * 2]     = o0;
    buf[tid * 2 + 1] = o1;
    __syncthreads();

    // ---- single bulk TMA store: 8KB contiguous per CTA ----
    // Output is flat: item i -> floats [i*8, i*8+8). K half then V half,
    // which i covers directly since V items have i >= NVEC.
    if (tid == 0) {
        float* gdst = out + (long long)blockIdx.x * (CTA_OUT_BYTES / 4);
        uint32_t saddr;
        asm volatile("{ .reg .u64 t; cvta.to.shared.u64 t, %1; cvt.u32.u64 %0, t; }"
                     : "=r"(saddr) : "l"(buf));
        asm volatile("fence.proxy.async.shared::cta;" ::: "memory");
        asm volatile("cp.async.bulk.global.shared::cta.bulk_group [%0], [%1], %2;"
                     :: "l"(gdst), "r"(saddr), "r"(CTA_OUT_BYTES) : "memory");
        asm volatile("cp.async.bulk.commit_group;" ::: "memory");
        // Wait until SMEM source has been fully read (safe to free SMEM at exit).
        asm volatile("cp.async.bulk.wait_group.read 0;" ::: "memory");
    }
}

extern "C" void kernel_launch(void* const* d_in, const int* in_sizes, int n_in,
                              void* d_out, int out_size)
{
    const int4*  kp = (const int4*) d_in[0];
    const float* ks = (const float*)d_in[1];
    const float* kb = (const float*)d_in[2];
    const int4*  vp = (const int4*) d_in[3];
    const float* vs = (const float*)d_in[4];
    const float* vb = (const float*)d_in[5];
    float* out = (float*)d_out;

    const int ctas = TOTAL / TPB;                          // 8192 CTAs
    kv_dequant_kernel<<<ctas, TPB>>>(kp, ks, kb, vp, vs, vb, out);
}